// round 3
// baseline (speedup 1.0000x reference)
#include <cuda_runtime.h>
#include <cuda_bf16.h>

#define NN 200000
#define NG 2048
#define INF 256
#define HID 512
#define OUTF 256

// Scratch (allocation-free rule: __device__ globals)
__device__ float g_h1[(size_t)NN * HID];      // 409.6 MB
__device__ float g_h2[(size_t)NN * HID];      // 409.6 MB
__device__ float g_pooled[NG * HID];          // 4 MB
__device__ float g_g1[NG * HID];              // 4 MB

// ---------------------------------------------------------------------------
// Tiled fp32 GEMM: C[M,N] = act(A[M,K] @ B[K,N] + bias[N])
// BM=128, BN=64, BK=16, 256 threads, 8x4 per-thread microtile.
// A row-major, B row-major [K,N] (weights are [fan_in, fan_out]).
// ---------------------------------------------------------------------------
template <bool RELU>
__global__ __launch_bounds__(256, 2) void gemm_bias(
    const float* __restrict__ A, const float* __restrict__ B,
    const float* __restrict__ bias, float* __restrict__ C,
    int M, int N, int K)
{
    constexpr int BM = 128, BN = 64, BK = 16, TM = 8, TN = 4;
    __shared__ float As[BK][BM + 4];   // transposed A tile, padded
    __shared__ float Bs[BK][BN];

    const int tid = threadIdx.x;
    const int rowBase = blockIdx.y * BM;
    const int colBase = blockIdx.x * BN;
    const int ty = tid >> 4;          // 0..15 -> row group (TM rows)
    const int tx = tid & 15;          // 0..15 -> col group (TN cols)

    float acc[TM][TN];
#pragma unroll
    for (int i = 0; i < TM; ++i)
#pragma unroll
        for (int j = 0; j < TN; ++j) acc[i][j] = 0.0f;

    // Per-thread A/B global load coordinates (loop-invariant)
    const int a_r0 = tid >> 2;                 // slot 0 row
    const int a_k0c = (tid & 3) << 2;          // slot 0 k-offset
    const int a_r1 = (tid + 256) >> 2;         // slot 1 row
    const int a_k1c = a_k0c;                   // same k pattern
    const int b_kr = tid >> 4;
    const int b_nc = (tid & 15) << 2;

    for (int k0 = 0; k0 < K; k0 += BK) {
        // --- global loads first (front-batched: MLP up) ---
        float4 va0 = make_float4(0.f, 0.f, 0.f, 0.f);
        float4 va1 = make_float4(0.f, 0.f, 0.f, 0.f);
        if (rowBase + a_r0 < M)
            va0 = *reinterpret_cast<const float4*>(A + (size_t)(rowBase + a_r0) * K + k0 + a_k0c);
        if (rowBase + a_r1 < M)
            va1 = *reinterpret_cast<const float4*>(A + (size_t)(rowBase + a_r1) * K + k0 + a_k1c);
        float4 vb = *reinterpret_cast<const float4*>(
            B + (size_t)(k0 + b_kr) * N + colBase + b_nc);

        // --- stores into smem ---
        As[a_k0c + 0][a_r0] = va0.x;
        As[a_k0c + 1][a_r0] = va0.y;
        As[a_k0c + 2][a_r0] = va0.z;
        As[a_k0c + 3][a_r0] = va0.w;
        As[a_k1c + 0][a_r1] = va1.x;
        As[a_k1c + 1][a_r1] = va1.y;
        As[a_k1c + 2][a_r1] = va1.z;
        As[a_k1c + 3][a_r1] = va1.w;
        *reinterpret_cast<float4*>(&Bs[b_kr][b_nc]) = vb;
        __syncthreads();

#pragma unroll
        for (int kk = 0; kk < BK; ++kk) {
            float4 a0 = *reinterpret_cast<const float4*>(&As[kk][ty * TM]);
            float4 a1 = *reinterpret_cast<const float4*>(&As[kk][ty * TM + 4]);
            float4 b0 = *reinterpret_cast<const float4*>(&Bs[kk][tx * TN]);
            float a[TM] = {a0.x, a0.y, a0.z, a0.w, a1.x, a1.y, a1.z, a1.w};
            float b[TN] = {b0.x, b0.y, b0.z, b0.w};
#pragma unroll
            for (int i = 0; i < TM; ++i)
#pragma unroll
                for (int j = 0; j < TN; ++j)
                    acc[i][j] = fmaf(a[i], b[j], acc[i][j]);
        }
        __syncthreads();
    }

    // --- epilogue: bias (+ReLU), float4 stores ---
    const int col = colBase + tx * TN;
    float4 bv = *reinterpret_cast<const float4*>(bias + col);
#pragma unroll
    for (int i = 0; i < TM; ++i) {
        int row = rowBase + ty * TM + i;
        if (row < M) {
            float4 o;
            o.x = acc[i][0] + bv.x;
            o.y = acc[i][1] + bv.y;
            o.z = acc[i][2] + bv.z;
            o.w = acc[i][3] + bv.w;
            if (RELU) {
                o.x = fmaxf(o.x, 0.f);
                o.y = fmaxf(o.y, 0.f);
                o.z = fmaxf(o.z, 0.f);
                o.w = fmaxf(o.w, 0.f);
            }
            *reinterpret_cast<float4*>(C + (size_t)row * N + col) = o;
        }
    }
}

// ---------------------------------------------------------------------------
// Segment-sum over sorted segment_ids: one block per graph, 128 threads,
// each thread owns 4 consecutive HID columns (float4). Row range found by
// binary search (redundant per thread; lives in L1/L2, cheap).
// ---------------------------------------------------------------------------
__global__ __launch_bounds__(128) void segment_pool(
    const float* __restrict__ h, const int* __restrict__ seg,
    float* __restrict__ pooled, int n_nodes)
{
    const int g = blockIdx.x;
    int lo = 0, hi = n_nodes;
    while (lo < hi) { int mid = (lo + hi) >> 1; if (seg[mid] < g) lo = mid + 1; else hi = mid; }
    const int start = lo;
    hi = n_nodes;
    while (lo < hi) { int mid = (lo + hi) >> 1; if (seg[mid] < g + 1) lo = mid + 1; else hi = mid; }
    const int end = lo;

    const int c = threadIdx.x << 2;      // column base 0..508
    float4 s = make_float4(0.f, 0.f, 0.f, 0.f);
    for (int r = start; r < end; ++r) {
        float4 v = *reinterpret_cast<const float4*>(h + (size_t)r * HID + c);
        s.x += v.x; s.y += v.y; s.z += v.z; s.w += v.w;
    }
    *reinterpret_cast<float4*>(pooled + (size_t)g * HID + c) = s;
}

// ---------------------------------------------------------------------------
// Launch
// inputs (metadata order): x, segment_ids, W1, b1, W2, b2, Wg1, bg1, Wg2, bg2
// output: [NG, OUTF] fp32
// ---------------------------------------------------------------------------
extern "C" void kernel_launch(void* const* d_in, const int* in_sizes, int n_in,
                              void* d_out, int out_size)
{
    const float* x   = (const float*)d_in[0];
    const int*   seg = (const int*)  d_in[1];
    const float* W1  = (const float*)d_in[2];
    const float* b1  = (const float*)d_in[3];
    const float* W2  = (const float*)d_in[4];
    const float* b2  = (const float*)d_in[5];
    const float* Wg1 = (const float*)d_in[6];
    const float* bg1 = (const float*)d_in[7];
    const float* Wg2 = (const float*)d_in[8];
    const float* bg2 = (const float*)d_in[9];
    float* out = (float*)d_out;

    float *h1, *h2, *pooled, *g1;
    cudaGetSymbolAddress((void**)&h1,     g_h1);
    cudaGetSymbolAddress((void**)&h2,     g_h2);
    cudaGetSymbolAddress((void**)&pooled, g_pooled);
    cudaGetSymbolAddress((void**)&g1,     g_g1);

    dim3 blk(256);
    dim3 grid1(HID / 64, (NN + 127) / 128);
    gemm_bias<true><<<grid1, blk>>>(x, W1, b1, h1, NN, HID, INF);

    dim3 grid2(HID / 64, (NN + 127) / 128);
    gemm_bias<true><<<grid2, blk>>>(h1, W2, b2, h2, NN, HID, HID);

    segment_pool<<<NG, 128>>>(h2, seg, pooled, NN);

    dim3 grid3(HID / 64, NG / 128);
    gemm_bias<true><<<grid3, blk>>>(pooled, Wg1, bg1, g1, NG, HID, HID);

    dim3 grid4(OUTF / 64, NG / 128);
    gemm_bias<false><<<grid4, blk>>>(g1, Wg2, bg2, out, NG, OUTF, HID);
}

// round 6
// speedup vs baseline: 4.2109x; 4.2109x over previous
#include <cuda_runtime.h>
#include <cuda_fp16.h>
#include <cuda_bf16.h>
#include <cstdint>

#define NN 200000
#define NG 2048
#define INF 256
#define HID 512
#define OUTF 256

// ---------------- scratch (__device__ globals: allocation-free rule) ----------
__device__ float g_h1[(size_t)NN * HID];
__device__ float g_h2[(size_t)NN * HID];
__device__ float g_pooled[NG * HID];
__device__ float g_g1[NG * HID];
__device__ __half g_w1t[HID * INF];   // W1^T [HID][INF] fp16
__device__ __half g_w2t[HID * HID];   // W2^T [HID][HID] fp16

// ---------------- tensor-core PTX (portable sm_80+: ldmatrix / mma.sync) -----
__device__ __forceinline__ uint32_t smem_u32(const void* p) {
    uint32_t a;
    asm("{ .reg .u64 t; cvta.to.shared.u64 t, %1; cvt.u32.u64 %0, t; }" : "=r"(a) : "l"(p));
    return a;
}
__device__ __forceinline__ void ldsm4(uint32_t* r, uint32_t addr) {
    asm volatile("ldmatrix.sync.aligned.m8n8.x4.shared.b16 {%0,%1,%2,%3}, [%4];"
                 : "=r"(r[0]), "=r"(r[1]), "=r"(r[2]), "=r"(r[3]) : "r"(addr));
}
__device__ __forceinline__ void ldsm2(uint32_t* r, uint32_t addr) {
    asm volatile("ldmatrix.sync.aligned.m8n8.x2.shared.b16 {%0,%1}, [%2];"
                 : "=r"(r[0]), "=r"(r[1]) : "r"(addr));
}
__device__ __forceinline__ void mma16816(float* d, const uint32_t* a, const uint32_t* b) {
    asm volatile(
        "mma.sync.aligned.m16n8k16.row.col.f32.f16.f16.f32 "
        "{%0,%1,%2,%3}, {%4,%5,%6,%7}, {%8,%9}, {%0,%1,%2,%3};"
        : "+f"(d[0]), "+f"(d[1]), "+f"(d[2]), "+f"(d[3])
        : "r"(a[0]), "r"(a[1]), "r"(a[2]), "r"(a[3]), "r"(b[0]), "r"(b[1]));
}

// ---------------------------------------------------------------------------
// fp16 tensor-core GEMM: C[M,N] = relu(A[M,K] @ Bt^T + bias)
// A fp32 (converted to fp16 on the LDG->STS path), Bt fp16 [N][K].
// Tile: BM=128, BN=128, BK=64, 256 threads (8 warps, 2x4 grid, warp 64x32).
// smem: 2 stages x (A 16KB + B 16KB) = 64KB, SW128 swizzle, one sync/iter.
// ---------------------------------------------------------------------------
template <bool RELU>
__global__ __launch_bounds__(256, 1) void hgemm(
    const float* __restrict__ A, const __half* __restrict__ Bt,
    const float* __restrict__ bias, float* __restrict__ C,
    int M, int N, int K)
{
    extern __shared__ char smem[];              // [stage][A 16KB | B 16KB]
    const uint32_t sbase = smem_u32(smem);
    const int tid = threadIdx.x, wid = tid >> 5, lane = tid & 31;
    const int wm = wid >> 2, wn = wid & 3;      // warp grid 2 x 4
    const int rowBase = blockIdx.y * 128, colBase = blockIdx.x * 128;

    float acc[4][4][4];
#pragma unroll
    for (int i = 0; i < 4; ++i)
#pragma unroll
        for (int j = 0; j < 4; ++j)
#pragma unroll
            for (int k = 0; k < 4; ++k) acc[i][j][k] = 0.0f;

    // ldmatrix lane-derived constants
    const int a_row = lane & 15;                // row within m16
    const int a_kb  = (lane >> 4) << 4;         // +0 / +16 bytes (k8 group)
    const int b_row = lane & 7;
    const int b_kb  = (lane & 8) << 1;          // +0 / +16 bytes

    const int nc = K >> 6;

    // per-thread global-load coords
    // A: 8 x float4; idx=i*256+tid; r=idx>>4 (16 float4/row), q=idx&15
    // B: 4 x uint4 (8 fp16); idx=i*256+tid; r=idx>>3, q=idx&7
    float4 va[8];
    uint4  vb[4];

    auto ldg = [&](int c) {
        const int k0 = c << 6;
#pragma unroll
        for (int i = 0; i < 8; ++i) {
            int idx = i * 256 + tid, r = idx >> 4, q = idx & 15, gr = rowBase + r;
            va[i] = (gr < M) ? *reinterpret_cast<const float4*>(A + (size_t)gr * K + k0 + q * 4)
                             : make_float4(0.f, 0.f, 0.f, 0.f);
        }
#pragma unroll
        for (int i = 0; i < 4; ++i) {
            int idx = i * 256 + tid, r = idx >> 3, q = idx & 7;
            vb[i] = *reinterpret_cast<const uint4*>(Bt + (size_t)(colBase + r) * K + k0 + q * 8);
        }
    };
    auto sts = [&](int stage) {
        char* stA = smem + stage * 32768;
        char* stB = stA + 16384;
#pragma unroll
        for (int i = 0; i < 8; ++i) {
            int idx = i * 256 + tid, r = idx >> 4, q = idx & 15;
            uint32_t off = r * 128 + ((q * 8) ^ ((r & 7) << 4));
            __half2 p0 = __floats2half2_rn(va[i].x, va[i].y);
            __half2 p1 = __floats2half2_rn(va[i].z, va[i].w);
            *reinterpret_cast<uint2*>(stA + off) =
                make_uint2(*reinterpret_cast<uint32_t*>(&p0), *reinterpret_cast<uint32_t*>(&p1));
        }
#pragma unroll
        for (int i = 0; i < 4; ++i) {
            int idx = i * 256 + tid, r = idx >> 3, q = idx & 7;
            uint32_t off = r * 128 + ((q * 16) ^ ((r & 7) << 4));
            *reinterpret_cast<uint4*>(stB + off) = vb[i];
        }
    };

    ldg(0);
    for (int c = 0; c < nc; ++c) {
        const int stage = c & 1;
        sts(stage);
        __syncthreads();
        if (c + 1 < nc) ldg(c + 1);

        const uint32_t baseA = sbase + stage * 32768;
        const uint32_t baseB = baseA + 16384;
#pragma unroll
        for (int ks = 0; ks < 4; ++ks) {
            uint32_t af[4][4], bf[4][2];
#pragma unroll
            for (int mt = 0; mt < 4; ++mt) {
                int row = wm * 64 + mt * 16 + a_row;
                ldsm4(af[mt], baseA + row * 128 + ((ks * 32 + a_kb) ^ ((row & 7) << 4)));
            }
#pragma unroll
            for (int nt = 0; nt < 4; ++nt) {
                int row = wn * 32 + nt * 8 + b_row;
                ldsm2(bf[nt], baseB + row * 128 + ((ks * 32 + b_kb) ^ ((row & 7) << 4)));
            }
#pragma unroll
            for (int mt = 0; mt < 4; ++mt)
#pragma unroll
                for (int nt = 0; nt < 4; ++nt)
                    mma16816(acc[mt][nt], af[mt], bf[nt]);
        }
        // single sync per iteration: a warp enters the NEXT iteration's sync
        // only after finishing this compute, so stage reuse (c+2) is safe.
    }

    // ---- epilogue: direct stores; each quad writes a contiguous 32B sector ----
    const int qr = lane >> 2, qc = (lane & 3) * 2;
#pragma unroll
    for (int nt = 0; nt < 4; ++nt) {
        const int cc = colBase + wn * 32 + nt * 8 + qc;
        const float2 bv = *reinterpret_cast<const float2*>(bias + cc);
#pragma unroll
        for (int mt = 0; mt < 4; ++mt) {
            const int r0 = rowBase + wm * 64 + mt * 16 + qr;
            float x0 = acc[mt][nt][0] + bv.x, x1 = acc[mt][nt][1] + bv.y;
            float x2 = acc[mt][nt][2] + bv.x, x3 = acc[mt][nt][3] + bv.y;
            if (RELU) {
                x0 = fmaxf(x0, 0.f); x1 = fmaxf(x1, 0.f);
                x2 = fmaxf(x2, 0.f); x3 = fmaxf(x3, 0.f);
            }
            if (r0 < M)
                *reinterpret_cast<float2*>(C + (size_t)r0 * N + cc) = make_float2(x0, x1);
            if (r0 + 8 < M)
                *reinterpret_cast<float2*>(C + (size_t)(r0 + 8) * N + cc) = make_float2(x2, x3);
        }
    }
}

// ---------------------------------------------------------------------------
// Weight transpose + fp16 convert: W[K][N] fp32 -> Wt[N][K] fp16
// ---------------------------------------------------------------------------
__global__ void wtrans(const float* __restrict__ W, __half* __restrict__ out, int K, int N)
{
    int idx = blockIdx.x * blockDim.x + threadIdx.x;
    if (idx < N * K) {
        int n = idx / K, k = idx - n * K;
        out[idx] = __float2half_rn(W[(size_t)k * N + n]);
    }
}

// ---------------------------------------------------------------------------
// fp32 SIMT GEMM (R3, known-good) for the small post-pooling graph MLP.
// ---------------------------------------------------------------------------
template <bool RELU>
__global__ __launch_bounds__(256, 2) void gemm_bias(
    const float* __restrict__ A, const float* __restrict__ B,
    const float* __restrict__ bias, float* __restrict__ C,
    int M, int N, int K)
{
    constexpr int BM = 128, BN = 64, BK = 16, TM = 8, TN = 4;
    __shared__ float As[BK][BM + 4];
    __shared__ float Bs[BK][BN];

    const int tid = threadIdx.x;
    const int rowBase = blockIdx.y * BM, colBase = blockIdx.x * BN;
    const int ty = tid >> 4, tx = tid & 15;

    float acc[TM][TN];
#pragma unroll
    for (int i = 0; i < TM; ++i)
#pragma unroll
        for (int j = 0; j < TN; ++j) acc[i][j] = 0.0f;

    const int a_r0 = tid >> 2, a_kc = (tid & 3) << 2, a_r1 = a_r0 + 64;
    const int b_kr = tid >> 4, b_nc = (tid & 15) << 2;

    for (int k0 = 0; k0 < K; k0 += BK) {
        float4 va0 = make_float4(0.f, 0.f, 0.f, 0.f), va1 = va0;
        if (rowBase + a_r0 < M)
            va0 = *reinterpret_cast<const float4*>(A + (size_t)(rowBase + a_r0) * K + k0 + a_kc);
        if (rowBase + a_r1 < M)
            va1 = *reinterpret_cast<const float4*>(A + (size_t)(rowBase + a_r1) * K + k0 + a_kc);
        float4 vb = *reinterpret_cast<const float4*>(B + (size_t)(k0 + b_kr) * N + colBase + b_nc);

        As[a_kc + 0][a_r0] = va0.x; As[a_kc + 1][a_r0] = va0.y;
        As[a_kc + 2][a_r0] = va0.z; As[a_kc + 3][a_r0] = va0.w;
        As[a_kc + 0][a_r1] = va1.x; As[a_kc + 1][a_r1] = va1.y;
        As[a_kc + 2][a_r1] = va1.z; As[a_kc + 3][a_r1] = va1.w;
        *reinterpret_cast<float4*>(&Bs[b_kr][b_nc]) = vb;
        __syncthreads();

#pragma unroll
        for (int kk = 0; kk < BK; ++kk) {
            float4 a0 = *reinterpret_cast<const float4*>(&As[kk][ty * TM]);
            float4 a1 = *reinterpret_cast<const float4*>(&As[kk][ty * TM + 4]);
            float4 b0 = *reinterpret_cast<const float4*>(&Bs[kk][tx * TN]);
            float a[TM] = {a0.x, a0.y, a0.z, a0.w, a1.x, a1.y, a1.z, a1.w};
            float b[TN] = {b0.x, b0.y, b0.z, b0.w};
#pragma unroll
            for (int i = 0; i < TM; ++i)
#pragma unroll
                for (int j = 0; j < TN; ++j)
                    acc[i][j] = fmaf(a[i], b[j], acc[i][j]);
        }
        __syncthreads();
    }

    const int col = colBase + tx * TN;
    float4 bv = *reinterpret_cast<const float4*>(bias + col);
#pragma unroll
    for (int i = 0; i < TM; ++i) {
        int row = rowBase + ty * TM + i;
        if (row < M) {
            float4 o;
            o.x = acc[i][0] + bv.x; o.y = acc[i][1] + bv.y;
            o.z = acc[i][2] + bv.z; o.w = acc[i][3] + bv.w;
            if (RELU) {
                o.x = fmaxf(o.x, 0.f); o.y = fmaxf(o.y, 0.f);
                o.z = fmaxf(o.z, 0.f); o.w = fmaxf(o.w, 0.f);
            }
            *reinterpret_cast<float4*>(C + (size_t)row * N + col) = o;
        }
    }
}

// ---------------------------------------------------------------------------
// Segment-sum (sorted ids): one block per graph, float4 per thread.
// ---------------------------------------------------------------------------
__global__ __launch_bounds__(128) void segment_pool(
    const float* __restrict__ h, const int* __restrict__ seg,
    float* __restrict__ pooled, int n_nodes)
{
    const int g = blockIdx.x;
    int lo = 0, hi = n_nodes;
    while (lo < hi) { int mid = (lo + hi) >> 1; if (seg[mid] < g) lo = mid + 1; else hi = mid; }
    const int start = lo;
    hi = n_nodes;
    while (lo < hi) { int mid = (lo + hi) >> 1; if (seg[mid] < g + 1) lo = mid + 1; else hi = mid; }
    const int end = lo;

    const int c = threadIdx.x << 2;
    float4 s = make_float4(0.f, 0.f, 0.f, 0.f);
    for (int r = start; r < end; ++r) {
        float4 v = *reinterpret_cast<const float4*>(h + (size_t)r * HID + c);
        s.x += v.x; s.y += v.y; s.z += v.z; s.w += v.w;
    }
    *reinterpret_cast<float4*>(pooled + (size_t)g * HID + c) = s;
}

// ---------------------------------------------------------------------------
#define HGEMM_SMEM 65536

extern "C" void kernel_launch(void* const* d_in, const int* in_sizes, int n_in,
                              void* d_out, int out_size)
{
    const float* x   = (const float*)d_in[0];
    const int*   seg = (const int*)  d_in[1];
    const float* W1  = (const float*)d_in[2];
    const float* b1  = (const float*)d_in[3];
    const float* W2  = (const float*)d_in[4];
    const float* b2  = (const float*)d_in[5];
    const float* Wg1 = (const float*)d_in[6];
    const float* bg1 = (const float*)d_in[7];
    const float* Wg2 = (const float*)d_in[8];
    const float* bg2 = (const float*)d_in[9];
    float* out = (float*)d_out;

    float *h1, *h2, *pooled, *g1;
    __half *w1t, *w2t;
    cudaGetSymbolAddress((void**)&h1, g_h1);
    cudaGetSymbolAddress((void**)&h2, g_h2);
    cudaGetSymbolAddress((void**)&pooled, g_pooled);
    cudaGetSymbolAddress((void**)&g1, g_g1);
    cudaGetSymbolAddress((void**)&w1t, g_w1t);
    cudaGetSymbolAddress((void**)&w2t, g_w2t);

    cudaFuncSetAttribute(hgemm<true>, cudaFuncAttributeMaxDynamicSharedMemorySize, HGEMM_SMEM);

    // weight transpose + fp16 convert (tiny)
    wtrans<<<(HID * INF + 255) / 256, 256>>>(W1, w1t, INF, HID);
    wtrans<<<(HID * HID + 255) / 256, 256>>>(W2, w2t, HID, HID);

    // node MLP: tensor cores (fp16 operands, fp32 accumulate)
    hgemm<true><<<dim3(HID / 128, (NN + 127) / 128), 256, HGEMM_SMEM>>>(
        x, w1t, b1, h1, NN, HID, INF);
    hgemm<true><<<dim3(HID / 128, (NN + 127) / 128), 256, HGEMM_SMEM>>>(
        h1, w2t, b2, h2, NN, HID, HID);

    // readout
    segment_pool<<<NG, 128>>>(h2, seg, pooled, NN);

    // graph MLP: fp32 SIMT (small; keeps precision headroom)
    gemm_bias<true><<<dim3(HID / 64, (NG + 127) / 128), 256>>>(
        pooled, Wg1, bg1, g1, NG, HID, HID);
    gemm_bias<false><<<dim3(OUTF / 64, (NG + 127) / 128), 256>>>(
        g1, Wg2, bg2, out, NG, OUTF, HID);
}

// round 7
// speedup vs baseline: 6.2761x; 1.4905x over previous
#include <cuda_runtime.h>
#include <cuda_fp16.h>
#include <cstdint>

#define NN 200000
#define NG 2048
#define INF 256
#define HID 512
#define OUTF 256

// ---------------- scratch (__device__ globals: allocation-free rule) ----------
__device__ __half g_x16[(size_t)NN * INF];     // 102.4 MB
__device__ __half g_h1[(size_t)NN * HID];      // 204.8 MB
__device__ __half g_h2[(size_t)NN * HID];      // 204.8 MB
__device__ __half g_pooled[NG * HID];
__device__ __half g_g1[NG * HID];
__device__ __half g_w1t[HID * INF];            // W1^T [HID][INF]
__device__ __half g_w2t[HID * HID];
__device__ __half g_wg1t[HID * HID];
__device__ __half g_wg2t[OUTF * HID];

// ---------------- PTX helpers (portable sm_80+) ----------------
__device__ __forceinline__ uint32_t smem_u32(const void* p) {
    uint32_t a;
    asm("{ .reg .u64 t; cvta.to.shared.u64 t, %1; cvt.u32.u64 %0, t; }" : "=r"(a) : "l"(p));
    return a;
}
__device__ __forceinline__ void cp_async16(uint32_t dst, const void* src, int src_bytes) {
    asm volatile("cp.async.cg.shared.global [%0], [%1], 16, %2;"
                 :: "r"(dst), "l"(src), "r"(src_bytes) : "memory");
}
__device__ __forceinline__ void cp_commit() {
    asm volatile("cp.async.commit_group;" ::: "memory");
}
__device__ __forceinline__ void cp_wait1() {
    asm volatile("cp.async.wait_group 1;" ::: "memory");
}
__device__ __forceinline__ void ldsm4(uint32_t* r, uint32_t addr) {
    asm volatile("ldmatrix.sync.aligned.m8n8.x4.shared.b16 {%0,%1,%2,%3}, [%4];"
                 : "=r"(r[0]), "=r"(r[1]), "=r"(r[2]), "=r"(r[3]) : "r"(addr));
}
__device__ __forceinline__ void ldsm2(uint32_t* r, uint32_t addr) {
    asm volatile("ldmatrix.sync.aligned.m8n8.x2.shared.b16 {%0,%1}, [%2];"
                 : "=r"(r[0]), "=r"(r[1]) : "r"(addr));
}
__device__ __forceinline__ void mma16816(float* d, const uint32_t* a, const uint32_t* b) {
    asm volatile(
        "mma.sync.aligned.m16n8k16.row.col.f32.f16.f16.f32 "
        "{%0,%1,%2,%3}, {%4,%5,%6,%7}, {%8,%9}, {%0,%1,%2,%3};"
        : "+f"(d[0]), "+f"(d[1]), "+f"(d[2]), "+f"(d[3])
        : "r"(a[0]), "r"(a[1]), "r"(a[2]), "r"(a[3]), "r"(b[0]), "r"(b[1]));
}

// ---------------------------------------------------------------------------
// fp16 tensor-core GEMM with cp.async 3-stage pipeline.
// C[M,N] = act(A[M,K] @ Bt^T + bias);  A,Bt fp16 row-major [*,K].
// Tile BM=128, BN=128, BK=64; 256 threads (8 warps, 2x4); 3 x 32KB smem.
// ---------------------------------------------------------------------------
#define HG_STAGE 32768
#define HG_SMEM  (3 * HG_STAGE)

template <bool RELU, bool OUT_HALF>
__global__ __launch_bounds__(256, 2) void hgemm(
    const __half* __restrict__ A, const __half* __restrict__ Bt,
    const float* __restrict__ bias, void* __restrict__ Cv,
    int M, int N, int K)
{
    extern __shared__ char smem[];
    const uint32_t sbase = smem_u32(smem);
    const int tid = threadIdx.x, wid = tid >> 5, lane = tid & 31;
    const int wm = wid >> 2, wn = wid & 3;      // warp grid 2 x 4 (64x32 per warp)
    const int rowBase = blockIdx.y * 128, colBase = blockIdx.x * 128;

    float acc[4][4][4];
#pragma unroll
    for (int i = 0; i < 4; ++i)
#pragma unroll
        for (int j = 0; j < 4; ++j)
#pragma unroll
            for (int k = 0; k < 4; ++k) acc[i][j][k] = 0.0f;

    const int a_row = lane & 15;
    const int a_kb  = (lane >> 4) << 4;
    const int b_row = lane & 7;
    const int b_kb  = (lane & 8) << 1;
    const int nc = K >> 6;

    // cp.async issue of one 64-k chunk into stage buffer
    auto issue = [&](int c) {
        const int stage = c % 3;
        const uint32_t stA = sbase + stage * HG_STAGE;
        const uint32_t stB = stA + 16384;
        const int k0 = c << 6;
#pragma unroll
        for (int j = 0; j < 4; ++j) {           // A: 128 rows x 128B
            int idx = j * 256 + tid, r = idx >> 3, q = idx & 7;
            int gr = rowBase + r;
            int sz = (gr < M) ? 16 : 0;
            if (gr >= M) gr = M - 1;            // safe address, zero-filled
            uint32_t dst = stA + r * 128 + ((q * 16) ^ ((r & 7) << 4));
            cp_async16(dst, A + (size_t)gr * K + k0 + q * 8, sz);
        }
#pragma unroll
        for (int j = 0; j < 4; ++j) {           // B: 128 rows x 128B
            int idx = j * 256 + tid, r = idx >> 3, q = idx & 7;
            uint32_t dst = stB + r * 128 + ((q * 16) ^ ((r & 7) << 4));
            cp_async16(dst, Bt + (size_t)(colBase + r) * K + k0 + q * 8, 16);
        }
        cp_commit();
    };

    issue(0);
    issue(1);

    for (int c = 0; c < nc; ++c) {
        cp_wait1();                 // stage c resident
        __syncthreads();

        const uint32_t baseA = sbase + (c % 3) * HG_STAGE;
        const uint32_t baseB = baseA + 16384;
#pragma unroll
        for (int ks = 0; ks < 4; ++ks) {
            uint32_t af[4][4], bf[4][2];
#pragma unroll
            for (int mt = 0; mt < 4; ++mt) {
                int row = wm * 64 + mt * 16 + a_row;
                ldsm4(af[mt], baseA + row * 128 + ((ks * 32 + a_kb) ^ ((row & 7) << 4)));
            }
#pragma unroll
            for (int nt = 0; nt < 4; ++nt) {
                int row = wn * 32 + nt * 8 + b_row;
                ldsm2(bf[nt], baseB + row * 128 + ((ks * 32 + b_kb) ^ ((row & 7) << 4)));
            }
#pragma unroll
            for (int mt = 0; mt < 4; ++mt)
#pragma unroll
                for (int nt = 0; nt < 4; ++nt)
                    mma16816(acc[mt][nt], af[mt], bf[nt]);
        }
        if (c + 2 < nc) issue(c + 2);
        // next iteration's __syncthreads (after cp_wait1) protects stage reuse
    }

    // ---- epilogue ----
    const int qr = lane >> 2, qc = (lane & 3) * 2;
#pragma unroll
    for (int nt = 0; nt < 4; ++nt) {
        const int cc = colBase + wn * 32 + nt * 8 + qc;
        const float2 bv = *reinterpret_cast<const float2*>(bias + cc);
#pragma unroll
        for (int mt = 0; mt < 4; ++mt) {
            const int r0 = rowBase + wm * 64 + mt * 16 + qr;
            float x0 = acc[mt][nt][0] + bv.x, x1 = acc[mt][nt][1] + bv.y;
            float x2 = acc[mt][nt][2] + bv.x, x3 = acc[mt][nt][3] + bv.y;
            if (RELU) {
                x0 = fmaxf(x0, 0.f); x1 = fmaxf(x1, 0.f);
                x2 = fmaxf(x2, 0.f); x3 = fmaxf(x3, 0.f);
            }
            if (OUT_HALF) {
                __half* C = (__half*)Cv;
                __half2 p0 = __floats2half2_rn(x0, x1);
                __half2 p1 = __floats2half2_rn(x2, x3);
                if (r0 < M)
                    *reinterpret_cast<uint32_t*>(C + (size_t)r0 * N + cc) =
                        *reinterpret_cast<uint32_t*>(&p0);
                if (r0 + 8 < M)
                    *reinterpret_cast<uint32_t*>(C + (size_t)(r0 + 8) * N + cc) =
                        *reinterpret_cast<uint32_t*>(&p1);
            } else {
                float* C = (float*)Cv;
                if (r0 < M)
                    *reinterpret_cast<float2*>(C + (size_t)r0 * N + cc) = make_float2(x0, x1);
                if (r0 + 8 < M)
                    *reinterpret_cast<float2*>(C + (size_t)(r0 + 8) * N + cc) = make_float2(x2, x3);
            }
        }
    }
}

// ---------------------------------------------------------------------------
__global__ void f2h(const float* __restrict__ in, __half* __restrict__ out, int n)
{
    int i = (blockIdx.x * blockDim.x + threadIdx.x) * 4;
    if (i < n) {
        float4 v = *reinterpret_cast<const float4*>(in + i);
        __half2 p0 = __floats2half2_rn(v.x, v.y);
        __half2 p1 = __floats2half2_rn(v.z, v.w);
        *reinterpret_cast<uint2*>(out + i) =
            make_uint2(*reinterpret_cast<uint32_t*>(&p0), *reinterpret_cast<uint32_t*>(&p1));
    }
}

__global__ void wtrans(const float* __restrict__ W, __half* __restrict__ out, int K, int N)
{
    int idx = blockIdx.x * blockDim.x + threadIdx.x;
    if (idx < N * K) {
        int n = idx / K, k = idx - n * K;
        out[idx] = __float2half_rn(W[(size_t)k * N + n]);
    }
}

// ---------------------------------------------------------------------------
// Segment-sum (sorted ids), fp16 in / fp32 accumulate / fp16 out.
// One block per graph; 128 threads x 4 columns.
// ---------------------------------------------------------------------------
__global__ __launch_bounds__(128) void segment_pool(
    const __half* __restrict__ h, const int* __restrict__ seg,
    __half* __restrict__ pooled, int n_nodes)
{
    const int g = blockIdx.x;
    int lo = 0, hi = n_nodes;
    while (lo < hi) { int mid = (lo + hi) >> 1; if (seg[mid] < g) lo = mid + 1; else hi = mid; }
    const int start = lo;
    hi = n_nodes;
    while (lo < hi) { int mid = (lo + hi) >> 1; if (seg[mid] < g + 1) lo = mid + 1; else hi = mid; }
    const int end = lo;

    const int c = threadIdx.x << 2;
    float4 s = make_float4(0.f, 0.f, 0.f, 0.f);
    for (int r = start; r < end; ++r) {
        uint2 u = *reinterpret_cast<const uint2*>(h + (size_t)r * HID + c);
        __half2 v0 = *reinterpret_cast<__half2*>(&u.x);
        __half2 v1 = *reinterpret_cast<__half2*>(&u.y);
        float2 f0 = __half22float2(v0), f1 = __half22float2(v1);
        s.x += f0.x; s.y += f0.y; s.z += f1.x; s.w += f1.y;
    }
    __half2 p0 = __floats2half2_rn(s.x, s.y);
    __half2 p1 = __floats2half2_rn(s.z, s.w);
    *reinterpret_cast<uint2*>(pooled + (size_t)g * HID + c) =
        make_uint2(*reinterpret_cast<uint32_t*>(&p0), *reinterpret_cast<uint32_t*>(&p1));
}

// ---------------------------------------------------------------------------
extern "C" void kernel_launch(void* const* d_in, const int* in_sizes, int n_in,
                              void* d_out, int out_size)
{
    const float* x   = (const float*)d_in[0];
    const int*   seg = (const int*)  d_in[1];
    const float* W1  = (const float*)d_in[2];
    const float* b1  = (const float*)d_in[3];
    const float* W2  = (const float*)d_in[4];
    const float* b2  = (const float*)d_in[5];
    const float* Wg1 = (const float*)d_in[6];
    const float* bg1 = (const float*)d_in[7];
    const float* Wg2 = (const float*)d_in[8];
    const float* bg2 = (const float*)d_in[9];
    float* out = (float*)d_out;

    __half *x16, *h1, *h2, *pooled, *g1, *w1t, *w2t, *wg1t, *wg2t;
    cudaGetSymbolAddress((void**)&x16, g_x16);
    cudaGetSymbolAddress((void**)&h1, g_h1);
    cudaGetSymbolAddress((void**)&h2, g_h2);
    cudaGetSymbolAddress((void**)&pooled, g_pooled);
    cudaGetSymbolAddress((void**)&g1, g_g1);
    cudaGetSymbolAddress((void**)&w1t, g_w1t);
    cudaGetSymbolAddress((void**)&w2t, g_w2t);
    cudaGetSymbolAddress((void**)&wg1t, g_wg1t);
    cudaGetSymbolAddress((void**)&wg2t, g_wg2t);

    cudaFuncSetAttribute(hgemm<true, true>,
                         cudaFuncAttributeMaxDynamicSharedMemorySize, HG_SMEM);
    cudaFuncSetAttribute(hgemm<false, false>,
                         cudaFuncAttributeMaxDynamicSharedMemorySize, HG_SMEM);

    // input conversion + weight transpose/convert
    f2h<<<((size_t)NN * INF / 4 + 255) / 256, 256>>>(x, x16, NN * INF);
    wtrans<<<(HID * INF + 255) / 256, 256>>>(W1, w1t, INF, HID);
    wtrans<<<(HID * HID + 255) / 256, 256>>>(W2, w2t, HID, HID);
    wtrans<<<(HID * HID + 255) / 256, 256>>>(Wg1, wg1t, HID, HID);
    wtrans<<<(OUTF * HID + 255) / 256, 256>>>(Wg2, wg2t, HID, OUTF);

    // node MLP (fp16 tensor cores, fp32 accumulate)
    hgemm<true, true><<<dim3(HID / 128, (NN + 127) / 128), 256, HG_SMEM>>>(
        x16, w1t, b1, h1, NN, HID, INF);
    hgemm<true, true><<<dim3(HID / 128, (NN + 127) / 128), 256, HG_SMEM>>>(
        h1, w2t, b2, h2, NN, HID, HID);

    // readout
    segment_pool<<<NG, 128>>>(h2, seg, pooled, NN);

    // graph MLP (same tensor-core kernel)
    hgemm<true, true><<<dim3(HID / 128, NG / 128), 256, HG_SMEM>>>(
        pooled, wg1t, bg1, g1, NG, HID, HID);
    hgemm<false, false><<<dim3(OUTF / 128, NG / 128), 256, HG_SMEM>>>(
        g1, wg2t, bg2, out, NG, OUTF, HID);
}